// round 4
// baseline (speedup 1.0000x reference)
#include <cuda_runtime.h>
#include <cstdint>

// Problem constants
#define NUM_E   1024
#define DIM     128
#define HW      4096          // 64*64
#define N_TOTAL 65536
#define NBLOCKS 512           // N_TOTAL / 128 (n-tile = 128)

// Output layout (flattened tuple, float32)
#define OFF_LOSS   8388608
#define OFF_IDX    8388609
#define OFF_COMMIT 8454145
#define OFF_CODE   8454146

__device__ float d_enorm[NUM_E];
__device__ float d_blockS[NBLOCKS];

// ---------------------------------------------------------------------------
// f32x2 packed helpers (FFMA2 path — only reachable via PTX)
// ---------------------------------------------------------------------------
__device__ __forceinline__ unsigned long long pack2(float lo, float hi) {
    unsigned long long r;
    asm("mov.b64 %0, {%1, %2};" : "=l"(r) : "f"(lo), "f"(hi));
    return r;
}
__device__ __forceinline__ void ffma2(unsigned long long& d,
                                      unsigned long long a,
                                      unsigned long long b) {
    asm("fma.rn.f32x2 %0, %1, %2, %0;" : "+l"(d) : "l"(a), "l"(b));
}
__device__ __forceinline__ void unpack2(unsigned long long v, float& lo, float& hi) {
    asm("mov.b64 {%0, %1}, %2;" : "=f"(lo), "=f"(hi) : "l"(v));
}

// ---------------------------------------------------------------------------
// Kernel 0: per-code squared norms ||e_k||^2
// ---------------------------------------------------------------------------
__global__ void enorm_kernel(const float* __restrict__ emb) {
    int k    = blockIdx.x * 8 + (threadIdx.x >> 5);
    int lane = threadIdx.x & 31;
    const float4* row = (const float4*)(emb + (size_t)k * DIM);
    float4 v = row[lane];
    float s = __fadd_rn(__fadd_rn(__fmul_rn(v.x, v.x), __fmul_rn(v.y, v.y)),
                        __fadd_rn(__fmul_rn(v.z, v.z), __fmul_rn(v.w, v.w)));
    #pragma unroll
    for (int o = 16; o; o >>= 1) s = __fadd_rn(s, __shfl_xor_sync(0xffffffffu, s, o));
    if (lane == 0) d_enorm[k] = s;
}

// ---------------------------------------------------------------------------
// Main kernel. 512 blocks x 256 threads, 1 CTA/SM.
// Block tile: n=128, k=1024 (4 kt-tiles of 256).
// Thread (tx,ty)=(t&15,t>>4): micro-tile 8 n (ty*8..+8) x 16 k (tx*16..+16),
// accumulated as 8x8 packed f32x2 pairs.
// ---------------------------------------------------------------------------
// SMEM (float offsets):
//   zsm  [128][128]          @0      (64KB, z tile [d][n])
//   esm  16 x 1024B swizzled @16384  (16KB, e chunk [d][k], k-tile 256)
//   candv[128][16]           @20480
//   candk[128][16]           @22528
//   idxsm[128]               @24576
//   wsum [8]                 @24704
//   z2sm [128]               @24712
#define SM_ZSM   0
#define SM_ESM   16384
#define SM_CANDV 20480
#define SM_CANDK 22528
#define SM_IDX   24576
#define SM_WSUM  24704
#define SM_Z2    24712
#define SMEM_FLOATS 24840
#define SMEM_BYTES  (SMEM_FLOATS * 4)

__global__ __launch_bounds__(256, 1)
void vq_main_kernel(const float* __restrict__ z,
                    const float* __restrict__ emb,
                    float* __restrict__ out) {
    extern __shared__ float smem[];
    float (*zsm)[128]   = (float (*)[128])(smem + SM_ZSM);
    char  *esmB         = (char*)(smem + SM_ESM);      // byte-addressed, swizzled
    float (*candv)[16]  = (float (*)[16])(smem + SM_CANDV);
    int   (*candk)[16]  = (int   (*)[16])(smem + SM_CANDK);
    int   *idxsm        = (int*)(smem + SM_IDX);
    float *wsum         = smem + SM_WSUM;
    float *z2sm         = smem + SM_Z2;

    const int t   = threadIdx.x;
    const int blk = blockIdx.x;
    const int n0  = blk * 128;
    const int b   = n0 >> 12;
    const int hw0 = n0 & 4095;
    const float* zbase = z + (size_t)b * (DIM * HW) + hw0;

    // ---- load z tile: zsm[d][n] (coalesced float4) ----
    {
        int n4 = (t & 31) * 4;
        #pragma unroll
        for (int i = 0; i < 16; i++) {
            int d = (t >> 5) + i * 8;
            float4 v = *(const float4*)(zbase + (size_t)d * HW + n4);
            *(float4*)(&zsm[d][n4]) = v;
        }
    }
    __syncthreads();

    // ---- z2[n]: strictly sequential fp32 sum over c (matches reference) ----
    if (t < 128) {
        float acc = 0.f;
        #pragma unroll 1
        for (int d = 0; d < 128; d++) {
            float v = zsm[d][t];
            acc = __fadd_rn(acc, __fmul_rn(v, v));
        }
        z2sm[t] = acc;
    }
    __syncthreads();

    const int tx = t & 15;
    const int ty = t >> 4;

    // swizzle constants (XOR of byte-bits[6:4] with bits[9:7]; both thread-const)
    const int st_xor = ((t >> 5) & 7) << 4;                  // store side: k = t
    const int st_low = (t * 4) ^ st_xor;                      // byte off within a d-row
    int ld_off[4];                                            // load side: 4 x 16B chunks
    #pragma unroll
    for (int q = 0; q < 4; q++)
        ld_off[q] = (tx * 64 + q * 16) ^ ((((tx * 64 + q * 16) >> 7) & 7) << 4);

    float z2r[8];
    #pragma unroll
    for (int i = 0; i < 8; i++) z2r[i] = z2sm[ty * 8 + i];

    float bestv[8];
    int   bestk[8];
    #pragma unroll
    for (int i = 0; i < 8; i++) { bestv[i] = 3.4e38f; bestk[i] = 0; }

    for (int kt = 0; kt < 4; kt++) {                          // k-tile of 256
        unsigned long long acc[8][8];                          // [n_i][k_pair]
        #pragma unroll
        for (int i = 0; i < 8; i++)
            #pragma unroll
            for (int p = 0; p < 8; p++) acc[i][p] = 0ull;

        for (int dc = 0; dc < 8; dc++) {                       // d chunks of 16
            __syncthreads();
            // load e chunk: 256 k x 16 d, transposed into swizzled esm[d][k]
            {
                const float* erow = emb + (size_t)(kt * 256 + t) * DIM + dc * 16;
                float4 a0 = *(const float4*)(erow);
                float4 a1 = *(const float4*)(erow + 4);
                float4 a2 = *(const float4*)(erow + 8);
                float4 a3 = *(const float4*)(erow + 12);
                float va[16] = {a0.x,a0.y,a0.z,a0.w, a1.x,a1.y,a1.z,a1.w,
                                a2.x,a2.y,a2.z,a2.w, a3.x,a3.y,a3.z,a3.w};
                #pragma unroll
                for (int dd = 0; dd < 16; dd++)
                    *(float*)(esmB + dd * 1024 + st_low) = va[dd];
            }
            __syncthreads();

            const int dglob = dc * 16;
            #pragma unroll
            for (int dd = 0; dd < 16; dd++) {
                float4 za = *(const float4*)(&zsm[dglob + dd][ty * 8]);
                float4 zb = *(const float4*)(&zsm[dglob + dd][ty * 8 + 4]);
                float zf[8] = {za.x, za.y, za.z, za.w, zb.x, zb.y, zb.z, zb.w};

                const char* eb = esmB + dd * 1024;
                ulonglong2 e0 = *(const ulonglong2*)(eb + ld_off[0]);
                ulonglong2 e1 = *(const ulonglong2*)(eb + ld_off[1]);
                ulonglong2 e2 = *(const ulonglong2*)(eb + ld_off[2]);
                ulonglong2 e3 = *(const ulonglong2*)(eb + ld_off[3]);
                unsigned long long pr[8] = {e0.x, e0.y, e1.x, e1.y,
                                            e2.x, e2.y, e3.x, e3.y};
                #pragma unroll
                for (int i = 0; i < 8; i++) {
                    unsigned long long zz = pack2(zf[i], zf[i]);
                    #pragma unroll
                    for (int p = 0; p < 8; p++)
                        ffma2(acc[i][p], zz, pr[p]);
                }
            }
        }

        // scoring: s = fl( fl(z2 + e2) - fl(2*dot) ); running first-min argmin
        #pragma unroll
        for (int p = 0; p < 8; p++) {
            int k0 = kt * 256 + tx * 16 + 2 * p;
            float en0 = d_enorm[k0];
            float en1 = d_enorm[k0 + 1];
            #pragma unroll
            for (int i = 0; i < 8; i++) {
                float d0, d1;
                unpack2(acc[i][p], d0, d1);
                float s0 = __fadd_rn(__fadd_rn(z2r[i], en0), __fmul_rn(-2.0f, d0));
                float s1 = __fadd_rn(__fadd_rn(z2r[i], en1), __fmul_rn(-2.0f, d1));
                if (s0 < bestv[i]) { bestv[i] = s0; bestk[i] = k0; }
                if (s1 < bestv[i]) { bestv[i] = s1; bestk[i] = k0 + 1; }
            }
        }
    }

    // ---- cross-thread argmin over the 16 tx candidates per n ----
    __syncthreads();
    #pragma unroll
    for (int i = 0; i < 8; i++) {
        candv[ty * 8 + i][tx] = bestv[i];
        candk[ty * 8 + i][tx] = bestk[i];
    }
    __syncthreads();
    if (t < 128) {
        float bv = candv[t][0];
        int   bk = candk[t][0];
        #pragma unroll
        for (int j = 1; j < 16; j++) {
            float v  = candv[t][j];
            int   kk = candk[t][j];
            if (v < bv || (v == bv && kk < bk)) { bv = v; bk = kk; }
        }
        idxsm[t] = bk;
        out[OFF_IDX + n0 + t] = (float)bk;
    }
    __syncthreads();

    // ---- epilogue: z_q gather + write (coalesced over n), partial S ----
    float sloc = 0.f;
    #pragma unroll 4
    for (int r = 0; r < 64; r++) {
        int linear = t + (r << 8);
        int d = linear >> 7;
        int n = linear & 127;
        float v    = emb[(size_t)idxsm[n] * DIM + d];
        float diff = v - zsm[d][n];
        sloc = fmaf(diff, diff, sloc);
        out[(size_t)b * (DIM * HW) + (size_t)d * HW + hw0 + n] = v;
    }
    #pragma unroll
    for (int o = 16; o; o >>= 1) sloc += __shfl_xor_sync(0xffffffffu, sloc, o);
    if ((t & 31) == 0) wsum[t >> 5] = sloc;
    __syncthreads();
    if (t == 0) {
        float s = 0.f;
        #pragma unroll
        for (int i = 0; i < 8; i++) s += wsum[i];
        d_blockS[blk] = s;
    }
}

// ---------------------------------------------------------------------------
__global__ void finalize_kernel(float* __restrict__ out) {
    __shared__ float sh[NBLOCKS];
    int t = threadIdx.x;
    sh[t] = d_blockS[t];
    __syncthreads();
    for (int s = NBLOCKS / 2; s > 0; s >>= 1) {
        if (t < s) sh[t] += sh[t + s];
        __syncthreads();
    }
    if (t == 0) {
        float S = sh[0];
        out[OFF_LOSS]   = 1.25f * S;
        out[OFF_COMMIT] = 0.25f * S;
        out[OFF_CODE]   = S;
    }
}

// ---------------------------------------------------------------------------
extern "C" void kernel_launch(void* const* d_in, const int* in_sizes, int n_in,
                              void* d_out, int out_size) {
    const float* z   = (const float*)d_in[0];   // (16, 128, 64, 64)
    const float* emb = (const float*)d_in[1];   // (1024, 128)
    float* out = (float*)d_out;

    cudaFuncSetAttribute(vq_main_kernel,
                         cudaFuncAttributeMaxDynamicSharedMemorySize,
                         SMEM_BYTES);

    enorm_kernel<<<128, 256>>>(emb);
    vq_main_kernel<<<NBLOCKS, 256, SMEM_BYTES>>>(z, emb, out);
    finalize_kernel<<<1, NBLOCKS>>>(out);
}